// round 1
// baseline (speedup 1.0000x reference)
#include <cuda_runtime.h>
#include <cstddef>

// Problem constants
#define BB     16
#define DD     512
#define HWV    1024            // H*W
#define NTOK   16384           // B*H*W
#define NB     256             // pass1 blocks
#define TPB    512             // pass1 threads/block
#define TILES_PER_BLK 2        // 256*2*32 tokens = 16384
#define TOKTILE 32             // tokens per tile
#define SSTRIDE 513            // smem row stride (conflict-free)

// Scratch (device globals — no allocation allowed)
// layout [q][d*NB + blk] so pass2 reads are coalesced
__device__ float  g_part[4][DD * NB];
__device__ float  g_br[NB];
__device__ double g_cd[DD];

// ---------------------------------------------------------------------------
// Pass 1: single sweep over all 100MB. Per (d) register accumulators:
//   Sinv[d]   = sum_i exp(-lv)
//   Smuinv[d] = sum_i mu*exp(-lv)
//   s1[d]     = sum_i x ,  s2[d] = sum_i x^2
// and a scalar bracket BR = sum_{i,d} (x^2 - 2 x mu) * exp(-lv)
// x is staged through SMEM (transposed tile) so both x and mu/lv reads are
// fully coalesced.
// ---------------------------------------------------------------------------
__global__ __launch_bounds__(TPB, 2)
void club_pass1(const float* __restrict__ x,
                const float* __restrict__ mu,
                const float* __restrict__ lv)
{
    extern __shared__ float sx[];      // TOKTILE * SSTRIDE floats = 65664 B
    const int tid = threadIdx.x;
    const int blk = blockIdx.x;

    float a_sinv = 0.f, a_smui = 0.f, a_s1 = 0.f, a_s2 = 0.f, a_br = 0.f;

    for (int tt = 0; tt < TILES_PER_BLK; tt++) {
        const int tile = blk * TILES_PER_BLK + tt;   // 0..511
        const int t0   = tile * TOKTILE;             // first token of tile
        const int b    = tile >> 5;                  // tile / 32
        const int s0   = (tile & 31) << 5;           // (tile%32)*32

        // ---- Phase A: load x tile [512 d x 32 s], transpose into SMEM ----
        const float* xb = x + (size_t)b * DD * HWV + s0;
        #pragma unroll
        for (int rep = 0; rep < 8; rep++) {
            int flat = rep * TPB + tid;              // 0..4095
            int d    = flat >> 3;
            int v4   = flat & 7;
            float4 v = *reinterpret_cast<const float4*>(xb + (size_t)d * HWV + v4 * 4);
            int r0 = v4 * 4;
            sx[(r0 + 0) * SSTRIDE + d] = v.x;
            sx[(r0 + 1) * SSTRIDE + d] = v.y;
            sx[(r0 + 2) * SSTRIDE + d] = v.z;
            sx[(r0 + 3) * SSTRIDE + d] = v.w;
        }
        __syncthreads();

        // ---- Phase B: thread <-> d, loop 32 tokens ----
        {
            const int d = tid;
            const float* mup = mu + (size_t)t0 * DD + d;
            const float* lvp = lv + (size_t)t0 * DD + d;
            #pragma unroll 4
            for (int ts = 0; ts < TOKTILE; ts++) {
                float m  = mup[ts * DD];
                float l  = lvp[ts * DD];
                float iv = expf(-l);
                float xv = sx[ts * SSTRIDE + d];
                a_sinv += iv;
                a_smui += m * iv;
                a_s1   += xv;
                a_s2   += xv * xv;
                a_br   += (xv - 2.0f * m) * xv * iv;
            }
        }
        __syncthreads();   // smem reused next tile / by reduction
    }

    // ---- write per-d partials (transposed layout for pass2 coalescing) ----
    {
        const int d = tid;
        g_part[0][(size_t)d * NB + blk] = a_sinv;
        g_part[1][(size_t)d * NB + blk] = a_smui;
        g_part[2][(size_t)d * NB + blk] = a_s1;
        g_part[3][(size_t)d * NB + blk] = a_s2;
    }

    // ---- block tree-reduce bracket (deterministic) ----
    sx[tid] = a_br;
    __syncthreads();
    #pragma unroll
    for (int off = TPB / 2; off > 0; off >>= 1) {
        if (tid < off) sx[tid] += sx[tid + off];
        __syncthreads();
    }
    if (tid == 0) g_br[blk] = sx[0];
}

// ---------------------------------------------------------------------------
// Pass 2: 64 blocks x 256 threads = 512 warps, warp <-> d.
// Reduce the NB=256 block-partials per d, form per-d double term:
//   c[d] = -m2[d]*Sinv[d] + 2*m1[d]*Smuinv[d]
// ---------------------------------------------------------------------------
__global__ void club_pass2()
{
    const int gw   = (blockIdx.x * blockDim.x + threadIdx.x) >> 5;  // 0..511
    const int lane = threadIdx.x & 31;
    const int d    = gw;

    float sinv = 0.f, smui = 0.f, s1 = 0.f, s2 = 0.f;
    #pragma unroll
    for (int k = 0; k < NB / 32; k++) {
        int blk = k * 32 + lane;                     // coalesced: blk contiguous
        sinv += g_part[0][(size_t)d * NB + blk];
        smui += g_part[1][(size_t)d * NB + blk];
        s1   += g_part[2][(size_t)d * NB + blk];
        s2   += g_part[3][(size_t)d * NB + blk];
    }
    #pragma unroll
    for (int off = 16; off > 0; off >>= 1) {
        sinv += __shfl_down_sync(0xFFFFFFFFu, sinv, off);
        smui += __shfl_down_sync(0xFFFFFFFFu, smui, off);
        s1   += __shfl_down_sync(0xFFFFFFFFu, s1,   off);
        s2   += __shfl_down_sync(0xFFFFFFFFu, s2,   off);
    }
    if (lane == 0) {
        double m1 = (double)s1 / (double)NTOK;
        double m2 = (double)s2 / (double)NTOK;
        g_cd[d] = -(m2 * (double)sinv) + 2.0 * m1 * (double)smui;
    }
}

// ---------------------------------------------------------------------------
// Pass 3: final deterministic double reduction -> scalar.
// loss = -0.5/N * ( BR_total + sum_d c[d] )
// ---------------------------------------------------------------------------
__global__ void club_pass3(float* __restrict__ out)
{
    __shared__ double sd[256];
    const int tid = threadIdx.x;
    double v = g_cd[tid] + g_cd[tid + 256] + (double)g_br[tid];
    sd[tid] = v;
    __syncthreads();
    #pragma unroll
    for (int off = 128; off > 0; off >>= 1) {
        if (tid < off) sd[tid] += sd[tid + off];
        __syncthreads();
    }
    if (tid == 0) out[0] = (float)(-0.5 / (double)NTOK * sd[0]);
}

// ---------------------------------------------------------------------------
extern "C" void kernel_launch(void* const* d_in, const int* in_sizes, int n_in,
                              void* d_out, int out_size)
{
    (void)in_sizes; (void)n_in; (void)out_size;
    const float* x  = (const float*)d_in[0];
    const float* mu = (const float*)d_in[1];
    const float* lv = (const float*)d_in[2];
    float* out = (float*)d_out;

    const int smem = TOKTILE * SSTRIDE * (int)sizeof(float);  // 65664 B
    cudaFuncSetAttribute(club_pass1, cudaFuncAttributeMaxDynamicSharedMemorySize, smem);

    club_pass1<<<NB, TPB, smem>>>(x, mu, lv);
    club_pass2<<<64, 256>>>();
    club_pass3<<<1, 256>>>(out);
}